// round 3
// baseline (speedup 1.0000x reference)
#include <cuda_runtime.h>

// lut_kernel_49538152792187 — 6-bit soft-LUT layer.
// x: [16, 2, 1024, 384] f32   (d_in[0])
// w: [1024, 64, 64]     f32   (d_in[1])
// out: [16, 2, 1024, 64] f32
//
// One thread per (out, lut) pair (65536 threads):
//   1. load 64-entry table w[out][lut][:], wq = sigmoid(2w) (== (tanh+1)/2),
//      fold level-0: y0[j]=wq[2j], d[j]=wq[2j+1]-wq[2j]  (64 persistent regs)
//   2. loop 32 (b,r) replicas: 3x LDG.64 bits (prefetched one iteration
//      ahead), 32 FFMA level-0, then 31 blends for levels 1..5.
// w read exactly once (no 32x amplification), no smem. Warp = 32 consecutive
// luts of one out => coalesced x spans (768B) and 128B output stores.

#define OUTN 1024
#define LUTN 64
#define BR 32

__device__ __forceinline__ float sig2(float v) {
    // (tanh(v)+1)/2 == 1/(1+exp(-2v)); randn v -> exp arg bounded, no overflow.
    float e = __expf(-2.0f * v);
    return __fdividef(1.0f, 1.0f + e);
}

__global__ void __launch_bounds__(64, 6)
lut_kernel(const float* __restrict__ x, const float* __restrict__ w,
           float* __restrict__ out) {
    const int t   = blockIdx.x * 64 + threadIdx.x;   // 0 .. 65535
    const int lut = t & (LUTN - 1);
    const int o   = t >> 6;                          // out index

    // ---- load table, compute wq, fold level 0 ----
    const float4* wp = reinterpret_cast<const float4*>(w + (size_t)t * 64);
    float y0[32], d[32];
#pragma unroll
    for (int i = 0; i < 16; i++) {
        float4 v = wp[i];
        float q0 = sig2(v.x), q1 = sig2(v.y), q2 = sig2(v.z), q3 = sig2(v.w);
        y0[2 * i]     = q0;  d[2 * i]     = q1 - q0;
        y0[2 * i + 1] = q2;  d[2 * i + 1] = q3 - q2;
    }

    const float* xp = x + (size_t)o * 384 + lut * 6;   // 8B-aligned (lut*24B)
    float*       op = out + (size_t)o * 64 + lut;
    const size_t xs = (size_t)OUTN * 384;              // stride between replicas
    const size_t os = (size_t)OUTN * 64;

    // prefetch iteration 0
    float2 a0 = *reinterpret_cast<const float2*>(xp);
    float2 a1 = *reinterpret_cast<const float2*>(xp + 2);
    float2 a2 = *reinterpret_cast<const float2*>(xp + 4);
    xp += xs;

#pragma unroll 4
    for (int br = 0; br < BR; br++) {
        float2 b0 = a0, b1 = a1, b2 = a2;
        if (br + 1 < BR) {                 // prefetch next replica's bits
            a0 = *reinterpret_cast<const float2*>(xp);
            a1 = *reinterpret_cast<const float2*>(xp + 2);
            a2 = *reinterpret_cast<const float2*>(xp + 4);
            xp += xs;
        }

        float y[32];
        // level 0: bit = b0.x, uses precomputed (y0, d)
#pragma unroll
        for (int j = 0; j < 32; j++) y[j] = fmaf(b0.x, d[j], y0[j]);
        // level 1
#pragma unroll
        for (int j = 0; j < 16; j++) y[j] = fmaf(b0.y, y[2 * j + 1] - y[2 * j], y[2 * j]);
        // level 2
#pragma unroll
        for (int j = 0; j < 8; j++)  y[j] = fmaf(b1.x, y[2 * j + 1] - y[2 * j], y[2 * j]);
        // level 3
#pragma unroll
        for (int j = 0; j < 4; j++)  y[j] = fmaf(b1.y, y[2 * j + 1] - y[2 * j], y[2 * j]);
        // level 4
#pragma unroll
        for (int j = 0; j < 2; j++)  y[j] = fmaf(b2.x, y[2 * j + 1] - y[2 * j], y[2 * j]);
        // level 5
        float r = fmaf(b2.y, y[1] - y[0], y[0]);

        *op = r;
        op += os;
    }
}

extern "C" void kernel_launch(void* const* d_in, const int* in_sizes, int n_in,
                              void* d_out, int out_size) {
    const float* x = (const float*)d_in[0];
    const float* w = (const float*)d_in[1];
    float* out = (float*)d_out;
    lut_kernel<<<(OUTN * LUTN) / 64, 64>>>(x, w, out);
}